// round 1
// baseline (speedup 1.0000x reference)
#include <cuda_runtime.h>
#include <math.h>

// ---------------------------------------------------------------------------
// SmallMLP ternary forward, sparse-gather formulation.
//   h  = relu(x @ tern(w1)^T + b1)          [8192, 4096]
//   s  = 127 / max(h)
//   hq = round(h*s)  (ints 0..127)
//   logits = (hq @ tern(w2)^T)/s + b2       [8192, 10]
//   out = log_softmax(logits)
// ---------------------------------------------------------------------------

#define B_     8192
#define DIN    784
#define DH     4096
#define DOUT   10

#define CAP1   96     // per-sign nonzero capacity per hidden neuron (mean ~18, max ~35)
#define CAP2   224    // per-sign capacity per output neuron (mean ~93, max ~125)

// Scratch (device globals: allocation-free rule)
__device__ float    g_h[(size_t)B_ * DH];          // 128 MB intermediate
__device__ int      g_idxp[DH * CAP1];
__device__ int      g_idxm[DH * CAP1];
__device__ int      g_cntp[DH];
__device__ int      g_cntm[DH];
__device__ int      g_w2p[DOUT * CAP2];
__device__ int      g_w2m[DOUT * CAP2];
__device__ int      g_w2cntp[DOUT];
__device__ int      g_w2cntm[DOUT];
__device__ unsigned g_maxbits;

// ---------------------------------------------------------------------------
__global__ void init_kernel() { g_maxbits = 0u; }

// Build per-neuron sparse +/- index lists for w1. One warp per neuron.
__global__ void build_w1_kernel(const float* __restrict__ w1) {
    int n = blockIdx.x * (blockDim.x >> 5) + (threadIdx.x >> 5);
    if (n >= DH) return;
    int lane = threadIdx.x & 31;
    int cp = 0, cm = 0;
    for (int k0 = 0; k0 < DIN; k0 += 32) {
        int k = k0 + lane;
        float w = (k < DIN) ? w1[(size_t)n * DIN + k] : 0.0f;
        bool ip = (w > 0.1f);
        bool im = (w < -0.1f);
        unsigned bp = __ballot_sync(0xFFFFFFFFu, ip);
        unsigned bm = __ballot_sync(0xFFFFFFFFu, im);
        unsigned pre = (1u << lane) - 1u;
        if (ip) { int p = cp + __popc(bp & pre); if (p < CAP1) g_idxp[n * CAP1 + p] = k; }
        if (im) { int p = cm + __popc(bm & pre); if (p < CAP1) g_idxm[n * CAP1 + p] = k; }
        cp += __popc(bp);
        cm += __popc(bm);
    }
    if (lane == 0) { g_cntp[n] = min(cp, CAP1); g_cntm[n] = min(cm, CAP1); }
}

// Same for w2 (10 neurons x 4096). One warp per output neuron.
__global__ void build_w2_kernel(const float* __restrict__ w2) {
    int n = blockIdx.x;
    if (n >= DOUT) return;
    int lane = threadIdx.x & 31;
    int cp = 0, cm = 0;
    for (int k0 = 0; k0 < DH; k0 += 32) {
        int k = k0 + lane;
        float w = w2[(size_t)n * DH + k];
        bool ip = (w > 0.1f);
        bool im = (w < -0.1f);
        unsigned bp = __ballot_sync(0xFFFFFFFFu, ip);
        unsigned bm = __ballot_sync(0xFFFFFFFFu, im);
        unsigned pre = (1u << lane) - 1u;
        if (ip) { int p = cp + __popc(bp & pre); if (p < CAP2) g_w2p[n * CAP2 + p] = k; }
        if (im) { int p = cm + __popc(bm & pre); if (p < CAP2) g_w2m[n * CAP2 + p] = k; }
        cp += __popc(bp);
        cm += __popc(bm);
    }
    if (lane == 0) { g_w2cntp[n] = min(cp, CAP2); g_w2cntm[n] = min(cm, CAP2); }
}

// ---------------------------------------------------------------------------
// GEMM1 (sparse): block = 32 m-rows x 1024 n-cols, 512 threads (16 warps).
// x tile [32 x 784] lives in SMEM with pitch 785 (785%32==17, coprime -> lanes
// (=m) hit distinct banks on every gather). Each warp handles 32-n groups:
// lane = m, serial over n in the group; results staged in a 32x33 SMEM tile,
// then stored transposed so the STG is a fully coalesced 128B row write.
// ---------------------------------------------------------------------------
#define G1_TM      32
#define G1_TN      1024
#define G1_WARPS   16
#define XS_PITCH   785
#define XS_FLOATS  (G1_TM * XS_PITCH)                 // 25120
#define HST_FLOATS (G1_WARPS * 32 * 33)               // 16896
#define G1_SMEM    ((XS_FLOATS + HST_FLOATS) * 4)     // 168064 bytes

__global__ void __launch_bounds__(512, 1)
gemm1_kernel(const float* __restrict__ x, const float* __restrict__ b1) {
    extern __shared__ float sm[];
    float* xs  = sm;
    float* hst = sm + XS_FLOATS;

    const int m0   = blockIdx.x * G1_TM;
    const int n0   = blockIdx.y * G1_TN;
    const int tid  = threadIdx.x;
    const int lane = tid & 31;
    const int wid  = tid >> 5;

    // cooperative x tile load (float4 from gmem, scalar STS due to odd pitch)
    const float4* x4 = (const float4*)x;
    for (int v = tid; v < G1_TM * (DIN / 4); v += 512) {
        int r = v / (DIN / 4);
        int c = v - r * (DIN / 4);
        float4 t = x4[(size_t)(m0 + r) * (DIN / 4) + c];
        float* d = xs + r * XS_PITCH + c * 4;
        d[0] = t.x; d[1] = t.y; d[2] = t.z; d[3] = t.w;
    }
    __syncthreads();

    const float* xrow = xs + lane * XS_PITCH;
    float* hw = hst + wid * (32 * 33);
    float lmax = 0.0f;

    for (int g = wid; g < G1_TN / 32; g += G1_WARPS) {
        const int nb = n0 + g * 32;
        for (int i = 0; i < 32; i++) {
            const int n = nb + i;
            const int cp = g_cntp[n];
            const int cm = g_cntm[n];
            const int4* lp4 = (const int4*)(g_idxp + n * CAP1);
            const int4* lm4 = (const int4*)(g_idxm + n * CAP1);
            float a0 = 0.f, a1 = 0.f, a2 = 0.f, a3 = 0.f;

            int cp4 = cp >> 2;
            for (int j = 0; j < cp4; j++) {
                int4 q = __ldg(lp4 + j);
                a0 += xrow[q.x]; a1 += xrow[q.y]; a2 += xrow[q.z]; a3 += xrow[q.w];
            }
            for (int j = cp4 * 4; j < cp; j++) a0 += xrow[__ldg(g_idxp + n * CAP1 + j)];

            int cm4 = cm >> 2;
            for (int j = 0; j < cm4; j++) {
                int4 q = __ldg(lm4 + j);
                a0 -= xrow[q.x]; a1 -= xrow[q.y]; a2 -= xrow[q.z]; a3 -= xrow[q.w];
            }
            for (int j = cm4 * 4; j < cm; j++) a0 -= xrow[__ldg(g_idxm + n * CAP1 + j)];

            float acc = (a0 + a1) + (a2 + a3) + __ldg(b1 + n);
            acc = fmaxf(acc, 0.0f);
            lmax = fmaxf(lmax, acc);
            hw[i * 33 + lane] = acc;
        }
        __syncwarp();
        // transposed, coalesced store: one 128B row per iteration
        #pragma unroll 4
        for (int r = 0; r < 32; r++) {
            g_h[(size_t)(m0 + r) * DH + nb + lane] = hw[lane * 33 + r];
        }
        __syncwarp();
    }

    // global max of relu(h): warp reduce + one atomic per warp (nonneg floats
    // compare identically as uint bit patterns)
    #pragma unroll
    for (int o = 16; o; o >>= 1) lmax = fmaxf(lmax, __shfl_xor_sync(0xFFFFFFFFu, lmax, o));
    if (lane == 0) atomicMax(&g_maxbits, __float_as_uint(lmax));
}

// ---------------------------------------------------------------------------
// Layer 2 + log_softmax. One block per sample row; quantize the h row into
// SMEM (integers 0..127 as floats -> exact accumulation), then each warp
// gathers the sparse w2 lists for its output neurons.
// ---------------------------------------------------------------------------
__global__ void __launch_bounds__(128, 8)
layer2_kernel(const float* __restrict__ b2, float* __restrict__ out) {
    __shared__ float q[DH];
    __shared__ float ls[DOUT];

    const int row  = blockIdx.x;
    const int tid  = threadIdx.x;
    const int lane = tid & 31;
    const int wid  = tid >> 5;

    const float maxh  = __uint_as_float(g_maxbits);
    const float scale = 127.0f / maxh;
    const float inv   = 1.0f / scale;

    const float4* h4 = (const float4*)(g_h + (size_t)row * DH);
    for (int v = tid; v < DH / 4; v += 128) {
        float4 t = h4[v];
        q[v * 4 + 0] = fminf(rintf(t.x * scale), 127.0f);
        q[v * 4 + 1] = fminf(rintf(t.y * scale), 127.0f);
        q[v * 4 + 2] = fminf(rintf(t.z * scale), 127.0f);
        q[v * 4 + 3] = fminf(rintf(t.w * scale), 127.0f);
    }
    __syncthreads();

    for (int n = wid; n < DOUT; n += 4) {
        const int cp = g_w2cntp[n];
        const int cm = g_w2cntm[n];
        const int* lp = g_w2p + n * CAP2;
        const int* lm = g_w2m + n * CAP2;
        float acc = 0.0f;
        for (int j = lane; j < cp; j += 32) acc += q[__ldg(lp + j)];
        for (int j = lane; j < cm; j += 32) acc -= q[__ldg(lm + j)];
        #pragma unroll
        for (int o = 16; o; o >>= 1) acc += __shfl_xor_sync(0xFFFFFFFFu, acc, o);
        if (lane == 0) ls[n] = acc * inv + __ldg(b2 + n);
    }
    __syncthreads();

    if (tid < DOUT) {
        float m = ls[0];
        #pragma unroll
        for (int i = 1; i < DOUT; i++) m = fmaxf(m, ls[i]);
        float s = 0.0f;
        #pragma unroll
        for (int i = 0; i < DOUT; i++) s += expf(ls[i] - m);
        out[(size_t)row * DOUT + tid] = ls[tid] - m - logf(s);
    }
}

// ---------------------------------------------------------------------------
extern "C" void kernel_launch(void* const* d_in, const int* in_sizes, int n_in,
                              void* d_out, int out_size) {
    const float* x  = (const float*)d_in[0];
    const float* w1 = (const float*)d_in[1];
    const float* b1 = (const float*)d_in[2];
    const float* w2 = (const float*)d_in[3];
    const float* b2 = (const float*)d_in[4];
    float* out = (float*)d_out;

    cudaFuncSetAttribute(gemm1_kernel,
                         cudaFuncAttributeMaxDynamicSharedMemorySize, G1_SMEM);

    init_kernel<<<1, 1>>>();
    build_w1_kernel<<<DH / 8, 256>>>(w1);   // 8 warps/block, warp per neuron
    build_w2_kernel<<<DOUT, 32>>>(w2);
    gemm1_kernel<<<dim3(B_ / G1_TM, DH / G1_TN), 512, G1_SMEM>>>(x, b1);
    layer2_kernel<<<B_, 128>>>(b2, out);
}

// round 2
// speedup vs baseline: 1.4455x; 1.4455x over previous
#include <cuda_runtime.h>
#include <math.h>

// ---------------------------------------------------------------------------
// SmallMLP ternary forward, sparse-gather formulation, v2.
//   h  = relu(x @ tern(w1)^T + b1)      stored TRANSPOSED: hT[n][m]
//   s  = 127 / max(h)
//   logits = (round(h*s) @ tern(w2)^T)/s + b2
//   out = log_softmax(logits)
// ---------------------------------------------------------------------------

#define B_     8192
#define DIN    784
#define DH     4096
#define DOUT   10

#define CAP1   64          // per-sign list capacity (ints), padded to mult of 4
#define XS_PITCH 785       // 785 % 32 = 17, coprime -> conflict-free lane=m gathers
#define ZOFF   (784*4)     // byte offset of the zero slot in each x row

#define G1_TM   32
#define G1_TN   512
#define G1_SMEM (G1_TM * XS_PITCH * 4)   // 100480 bytes -> 2 blocks/SM

#define NSPL   8           // layer-2 n-splits

// Scratch (device globals: allocation-free rule)
__device__ float    g_hT[(size_t)DH * B_];     // transposed hidden, 134 MB
__device__ int      g_idxp[DH * CAP1];         // byte offsets (k*4), zero-padded
__device__ int      g_idxm[DH * CAP1];
__device__ int2     g_cnt[DH];                 // {cp4, cm4} int4-chunk counts
__device__ int      g_nzn[DH];                 // nonzero w2 columns
__device__ unsigned g_nzw[DH];                 // packed signs: bit o = +, bit 16+o = -
__device__ int      g_nnzc;
__device__ float    g_logits[B_ * 16];         // raw integer-valued sums
__device__ unsigned g_maxbits;

// ---------------------------------------------------------------------------
__global__ void init_kernel() { g_maxbits = 0u; g_nnzc = 0; }

__global__ void l2init_kernel() {
    g_logits[blockIdx.x * 512 + threadIdx.x] = 0.0f;
}

// Build per-neuron sparse +/- byte-offset lists for w1. One warp per neuron.
__global__ void build_w1_kernel(const float* __restrict__ w1) {
    int n = blockIdx.x * (blockDim.x >> 5) + (threadIdx.x >> 5);
    if (n >= DH) return;
    int lane = threadIdx.x & 31;
    int cp = 0, cm = 0;
    for (int k0 = 0; k0 < DIN; k0 += 32) {
        int k = k0 + lane;
        float w = (k < DIN) ? w1[(size_t)n * DIN + k] : 0.0f;
        bool ip = (w > 0.1f);
        bool im = (w < -0.1f);
        unsigned bp = __ballot_sync(0xFFFFFFFFu, ip);
        unsigned bm = __ballot_sync(0xFFFFFFFFu, im);
        unsigned pre = (1u << lane) - 1u;
        if (ip) { int p = cp + __popc(bp & pre); if (p < CAP1) g_idxp[n * CAP1 + p] = k * 4; }
        if (im) { int p = cm + __popc(bm & pre); if (p < CAP1) g_idxm[n * CAP1 + p] = k * 4; }
        cp += __popc(bp);
        cm += __popc(bm);
    }
    cp = min(cp, CAP1 - 3);
    cm = min(cm, CAP1 - 3);
    // zero-pad to multiple of 4 with the zero-slot offset
    int padp = (4 - (cp & 3)) & 3;
    int padm = (4 - (cm & 3)) & 3;
    if (lane < padp) g_idxp[n * CAP1 + cp + lane] = ZOFF;
    if (lane < padm) g_idxm[n * CAP1 + cm + lane] = ZOFF;
    if (lane == 0) { g_cnt[n] = make_int2((cp + padp) >> 2, (cm + padm) >> 2); }
}

// Build packed ternary COLUMNS of w2, compacting the ~37% nonzero columns.
__global__ void build_w2col_kernel(const float* __restrict__ w2) {
    int n = blockIdx.x * 256 + threadIdx.x;
    if (n >= DH) return;
    unsigned cw = 0;
    #pragma unroll
    for (int o = 0; o < DOUT; o++) {
        float w = w2[(size_t)o * DH + n];
        if (w >  0.1f) cw |= 1u << o;
        if (w < -0.1f) cw |= 1u << (16 + o);
    }
    if (cw) {
        int p = atomicAdd(&g_nnzc, 1);
        g_nzn[p] = n;
        g_nzw[p] = cw;
    }
}

// ---------------------------------------------------------------------------
// GEMM1 (sparse): block = 32 m-rows x 512 n-cols, 512 threads, 100.5KB smem
// -> 2 blocks/SM. lane = m (conflict-free smem gathers, pitch coprime to 32).
// Per neuron: interleaved +/- int4 chunk loops, 8 independent FADD chains,
// zero-padded lists (no tails). Result column stored coalesced to hT[n][m].
// ---------------------------------------------------------------------------
__global__ void __launch_bounds__(512, 2)
gemm1_kernel(const float* __restrict__ x, const float* __restrict__ b1) {
    extern __shared__ float xs[];

    const int m0   = blockIdx.x * G1_TM;
    const int n0   = blockIdx.y * G1_TN;
    const int tid  = threadIdx.x;
    const int lane = tid & 31;
    const int wid  = tid >> 5;

    // cooperative x tile load (float4 from gmem, scalar STS due to odd pitch)
    const float4* x4 = (const float4*)x;
    for (int v = tid; v < G1_TM * (DIN / 4); v += 512) {
        int r = v / (DIN / 4);
        int c = v - r * (DIN / 4);
        float4 t = x4[(size_t)(m0 + r) * (DIN / 4) + c];
        float* d = xs + r * XS_PITCH + c * 4;
        d[0] = t.x; d[1] = t.y; d[2] = t.z; d[3] = t.w;
    }
    if (tid < G1_TM) xs[tid * XS_PITCH + 784] = 0.0f;   // zero slot for padding
    __syncthreads();

    const char* xb = (const char*)(xs + lane * XS_PITCH);
    float lmax = 0.0f;

    for (int n = n0 + wid; n < n0 + G1_TN; n += 16) {
        const int2 c = __ldg(&g_cnt[n]);
        const int4* lp = (const int4*)(g_idxp + n * CAP1);
        const int4* lm = (const int4*)(g_idxm + n * CAP1);

        float p0 = 0.f, p1 = 0.f, p2 = 0.f, p3 = 0.f;
        float q0 = 0.f, q1 = 0.f, q2 = 0.f, q3 = 0.f;

        const int jmax = max(c.x, c.y);
        for (int j = 0; j < jmax; j++) {
            if (j < c.x) {
                int4 t = __ldg(lp + j);
                p0 += *(const float*)(xb + t.x);
                p1 += *(const float*)(xb + t.y);
                p2 += *(const float*)(xb + t.z);
                p3 += *(const float*)(xb + t.w);
            }
            if (j < c.y) {
                int4 t = __ldg(lm + j);
                q0 += *(const float*)(xb + t.x);
                q1 += *(const float*)(xb + t.y);
                q2 += *(const float*)(xb + t.z);
                q3 += *(const float*)(xb + t.w);
            }
        }
        float acc = ((p0 + p1) + (p2 + p3)) - ((q0 + q1) + (q2 + q3)) + __ldg(b1 + n);
        acc = fmaxf(acc, 0.0f);
        lmax = fmaxf(lmax, acc);
        g_hT[(size_t)n * B_ + m0 + lane] = acc;   // coalesced 128B store
    }

    // global max of relu(h): warp reduce + one atomic per warp (nonneg floats
    // compare identically as uint bit patterns)
    #pragma unroll
    for (int o = 16; o; o >>= 1) lmax = fmaxf(lmax, __shfl_xor_sync(0xFFFFFFFFu, lmax, o));
    if (lane == 0) atomicMax(&g_maxbits, __float_as_uint(lmax));
}

// ---------------------------------------------------------------------------
// Layer 2 partial sums: thread owns one m, streams the nonzero w2 columns of
// its n-split; hT loads are fully coalesced. Accumulators hold exact integer
// values -> atomicAdd order doesn't matter.
// ---------------------------------------------------------------------------
__global__ void __launch_bounds__(512)
l2_partial_kernel() {
    const int m   = blockIdx.x * 512 + threadIdx.x;
    const int nn  = g_nnzc;
    const int per = (nn + NSPL - 1) / NSPL;
    const int c0  = blockIdx.y * per;
    const int c1  = min(c0 + per, nn);

    const float scale = 127.0f / __uint_as_float(g_maxbits);

    float acc[DOUT];
    #pragma unroll
    for (int o = 0; o < DOUT; o++) acc[o] = 0.0f;

    for (int c = c0; c < c1; c++) {
        const int      n  = __ldg(g_nzn + c);
        const unsigned cw = __ldg(g_nzw + c);
        const float    v  = __ldg(g_hT + (size_t)n * B_ + m);
        const float    q  = fminf(rintf(v * scale), 127.0f);
        #pragma unroll
        for (int o = 0; o < DOUT; o++) {
            if (cw & (1u << o))        acc[o] += q;
            if (cw & (1u << (16 + o))) acc[o] -= q;
        }
    }
    #pragma unroll
    for (int o = 0; o < DOUT; o++)
        if (acc[o] != 0.0f) atomicAdd(&g_logits[m * 16 + o], acc[o]);
}

// ---------------------------------------------------------------------------
__global__ void __launch_bounds__(256)
softmax_kernel(const float* __restrict__ b2, float* __restrict__ out) {
    const int m = blockIdx.x * 256 + threadIdx.x;
    const float inv = __uint_as_float(g_maxbits) * (1.0f / 127.0f);

    float l[DOUT];
    float mx = -1e30f;
    #pragma unroll
    for (int o = 0; o < DOUT; o++) {
        l[o] = g_logits[m * 16 + o] * inv + __ldg(b2 + o);
        mx = fmaxf(mx, l[o]);
    }
    float s = 0.0f;
    #pragma unroll
    for (int o = 0; o < DOUT; o++) s += expf(l[o] - mx);
    const float ls = logf(s);
    #pragma unroll
    for (int o = 0; o < DOUT; o++) out[(size_t)m * DOUT + o] = l[o] - mx - ls;
}

// ---------------------------------------------------------------------------
extern "C" void kernel_launch(void* const* d_in, const int* in_sizes, int n_in,
                              void* d_out, int out_size) {
    const float* x  = (const float*)d_in[0];
    const float* w1 = (const float*)d_in[1];
    const float* b1 = (const float*)d_in[2];
    const float* w2 = (const float*)d_in[3];
    const float* b2 = (const float*)d_in[4];
    float* out = (float*)d_out;

    cudaFuncSetAttribute(gemm1_kernel,
                         cudaFuncAttributeMaxDynamicSharedMemorySize, G1_SMEM);

    init_kernel<<<1, 1>>>();
    l2init_kernel<<<(B_ * 16) / 512, 512>>>();
    build_w1_kernel<<<DH / 8, 256>>>(w1);
    build_w2col_kernel<<<DH / 256, 256>>>(w2);
    gemm1_kernel<<<dim3(B_ / G1_TM, DH / G1_TN), 512, G1_SMEM>>>(x, b1);
    l2_partial_kernel<<<dim3(B_ / 512, NSPL), 512>>>();
    softmax_kernel<<<B_ / 256, 256>>>(b2, out);
}

// round 3
// speedup vs baseline: 1.6649x; 1.1518x over previous
#include <cuda_runtime.h>
#include <math.h>

// ---------------------------------------------------------------------------
// SmallMLP ternary forward, sparse-gather formulation, v3.
//   h  = relu(x @ tern(w1)^T + b1)   -> only w2-live columns stored (compact)
//   s  = 127 / max(h)                -> max over ALL of h, in-register
//   logits = (round(h*s) @ tern(w2)^T)/s + b2
//   out = log_softmax(logits)
// ---------------------------------------------------------------------------

#define B_     8192
#define DIN    784
#define DH     4096
#define DOUT   10

#define CAP1   64          // per-sign list capacity (ints), padded to mult of 4
#define XS_PITCH 785       // 785 % 32 = 17, coprime -> conflict-free lane=m gathers
#define ZOFF   (784*4)     // byte offset of the zero slot in each x row

#define G1_TM   32
#define G1_TN   512
#define G1_SMEM (G1_TM * XS_PITCH * 4)   // 100480 bytes -> 2 blocks/SM

#define NSPL   16          // layer-2 column splits

// Scratch (device globals: allocation-free rule)
__device__ float    g_hT2[(size_t)DH * B_];    // compacted transposed hidden
__device__ int      g_idxp[DH * CAP1];         // byte offsets (k*4), zero-padded
__device__ int      g_idxm[DH * CAP1];
__device__ int2     g_cnt[DH];                 // {cp4, cm4} int4-chunk counts (>=1)
__device__ int      g_slot[DH];                // compact slot or -1
__device__ unsigned g_nzw2[DH];                // packed w2 signs per compact slot
__device__ int      g_nnzc;
__device__ float    g_logits[B_ * 16];         // raw integer-valued sums
__device__ unsigned g_maxbits;

// ---------------------------------------------------------------------------
__global__ void init_kernel() { g_maxbits = 0u; g_nnzc = 0; }

__global__ void l2init_kernel() {
    g_logits[blockIdx.x * 512 + threadIdx.x] = 0.0f;
}

// Build per-neuron sparse +/- byte-offset lists for w1. One warp per neuron.
// Lists are padded with the zero-slot offset to a multiple of 4 (>= 4).
__global__ void build_w1_kernel(const float* __restrict__ w1) {
    int n = blockIdx.x * (blockDim.x >> 5) + (threadIdx.x >> 5);
    if (n >= DH) return;
    int lane = threadIdx.x & 31;
    int cp = 0, cm = 0;
    for (int k0 = 0; k0 < DIN; k0 += 32) {
        int k = k0 + lane;
        float w = (k < DIN) ? w1[(size_t)n * DIN + k] : 0.0f;
        bool ip = (w > 0.1f);
        bool im = (w < -0.1f);
        unsigned bp = __ballot_sync(0xFFFFFFFFu, ip);
        unsigned bm = __ballot_sync(0xFFFFFFFFu, im);
        unsigned pre = (1u << lane) - 1u;
        if (ip) { int p = cp + __popc(bp & pre); if (p < CAP1) g_idxp[n * CAP1 + p] = k * 4; }
        if (im) { int p = cm + __popc(bm & pre); if (p < CAP1) g_idxm[n * CAP1 + p] = k * 4; }
        cp += __popc(bp);
        cm += __popc(bm);
    }
    cp = min(cp, CAP1 - 4);
    cm = min(cm, CAP1 - 4);
    int cpp = (cp + 3) & ~3; if (cpp == 0) cpp = 4;
    int cmp = (cm + 3) & ~3; if (cmp == 0) cmp = 4;
    if (lane < cpp - cp) g_idxp[n * CAP1 + cp + lane] = ZOFF;
    if (lane < cmp - cm) g_idxm[n * CAP1 + cm + lane] = ZOFF;
    if (lane == 0) g_cnt[n] = make_int2(cpp >> 2, cmp >> 2);
}

// Build packed ternary COLUMNS of w2, compacting the nonzero columns.
__global__ void build_w2col_kernel(const float* __restrict__ w2) {
    int n = blockIdx.x * 256 + threadIdx.x;
    if (n >= DH) return;
    unsigned cw = 0;
    #pragma unroll
    for (int o = 0; o < DOUT; o++) {
        float w = w2[(size_t)o * DH + n];
        if (w >  0.1f) cw |= 1u << o;
        if (w < -0.1f) cw |= 1u << (16 + o);
    }
    if (cw) {
        int p = atomicAdd(&g_nnzc, 1);
        g_nzw2[p] = cw;
        g_slot[n] = p;
    } else {
        g_slot[n] = -1;
    }
}

// ---------------------------------------------------------------------------
// GEMM1 (sparse): block = 32 m-rows x 512 n-cols, 512 threads, 100.5KB smem
// -> 2 blocks/SM (50% occ). lane = m.
// Latency engineering: each warp preloads cnt/slot/b1 for ALL 32 of its
// neurons up-front (lane-parallel, shfl at use), and the chunk loop is
// software-pipelined (chunk j+1 int4 LDG issued while chunk j accumulates).
// ---------------------------------------------------------------------------
__global__ void __launch_bounds__(512, 2)
gemm1_kernel(const float* __restrict__ x, const float* __restrict__ b1) {
    extern __shared__ float xs[];

    const int m0   = blockIdx.x * G1_TM;
    const int n0   = blockIdx.y * G1_TN;
    const int tid  = threadIdx.x;
    const int lane = tid & 31;
    const int wid  = tid >> 5;

    // cooperative x tile load
    const float4* x4 = (const float4*)x;
    for (int v = tid; v < G1_TM * (DIN / 4); v += 512) {
        int r = v / (DIN / 4);
        int c = v - r * (DIN / 4);
        float4 t = x4[(size_t)(m0 + r) * (DIN / 4) + c];
        float* d = xs + r * XS_PITCH + c * 4;
        d[0] = t.x; d[1] = t.y; d[2] = t.z; d[3] = t.w;
    }
    if (tid < G1_TM) xs[tid * XS_PITCH + 784] = 0.0f;   // zero slot for padding
    __syncthreads();

    // Per-warp metadata preload: lane i holds iteration i's neuron metadata.
    const int nl = n0 + wid + 16 * lane;
    const int2  cnl = __ldg(&g_cnt[nl]);
    const int   sll = __ldg(&g_slot[nl]);
    const float b1l = __ldg(b1 + nl);

    const char* xb = (const char*)(xs + lane * XS_PITCH);
    float lmax = 0.0f;

    #pragma unroll 1
    for (int i = 0; i < 32; i++) {
        const int   n    = n0 + wid + 16 * i;
        const int   cp4  = __shfl_sync(0xFFFFFFFFu, cnl.x, i);
        const int   cm4  = __shfl_sync(0xFFFFFFFFu, cnl.y, i);
        const int   slot = __shfl_sync(0xFFFFFFFFu, sll, i);
        const float bv   = __shfl_sync(0xFFFFFFFFu, b1l, i);

        const int4* lp = (const int4*)(g_idxp + n * CAP1);
        const int4* lm = (const int4*)(g_idxm + n * CAP1);

        int4 tp = __ldg(lp);      // cp4 >= 1 guaranteed
        int4 tm = __ldg(lm);      // cm4 >= 1 guaranteed

        float p0 = 0.f, p1 = 0.f, p2 = 0.f, p3 = 0.f;
        float q0 = 0.f, q1 = 0.f, q2 = 0.f, q3 = 0.f;

        const int jmax = max(cp4, cm4);
        #pragma unroll 1
        for (int j = 0; j < jmax; j++) {
            const int4 fp_ = tp;
            const int4 fm_ = tm;
            if (j + 1 < cp4) tp = __ldg(lp + j + 1);   // prefetch next chunks
            if (j + 1 < cm4) tm = __ldg(lm + j + 1);
            if (j < cp4) {
                p0 += *(const float*)(xb + fp_.x);
                p1 += *(const float*)(xb + fp_.y);
                p2 += *(const float*)(xb + fp_.z);
                p3 += *(const float*)(xb + fp_.w);
            }
            if (j < cm4) {
                q0 += *(const float*)(xb + fm_.x);
                q1 += *(const float*)(xb + fm_.y);
                q2 += *(const float*)(xb + fm_.z);
                q3 += *(const float*)(xb + fm_.w);
            }
        }
        float acc = ((p0 + p1) + (p2 + p3)) - ((q0 + q1) + (q2 + q3)) + bv;
        acc = fmaxf(acc, 0.0f);
        lmax = fmaxf(lmax, acc);
        if (slot >= 0)
            g_hT2[(size_t)slot * B_ + m0 + lane] = acc;   // coalesced 128B store
    }

    // global max: warp reduce + one atomic per warp (nonneg float == uint order)
    #pragma unroll
    for (int o = 16; o; o >>= 1) lmax = fmaxf(lmax, __shfl_xor_sync(0xFFFFFFFFu, lmax, o));
    if (lane == 0) atomicMax(&g_maxbits, __float_as_uint(lmax));
}

// ---------------------------------------------------------------------------
// Layer 2 partial sums over compacted columns. Thread owns one m; hT2 loads
// are dense, coalesced streams. Accumulators are exact integers -> atomicAdd
// order-independent.
// ---------------------------------------------------------------------------
__global__ void __launch_bounds__(512)
l2_partial_kernel() {
    const int m   = blockIdx.x * 512 + threadIdx.x;
    const int nn  = g_nnzc;
    const int per = (nn + NSPL - 1) / NSPL;
    const int c0  = blockIdx.y * per;
    const int c1  = min(c0 + per, nn);

    const float scale = 127.0f / __uint_as_float(g_maxbits);

    float acc[DOUT];
    #pragma unroll
    for (int o = 0; o < DOUT; o++) acc[o] = 0.0f;

    for (int c = c0; c < c1; c++) {
        const unsigned cw = __ldg(g_nzw2 + c);
        const float    v  = __ldg(g_hT2 + (size_t)c * B_ + m);
        const float    q  = fminf(rintf(v * scale), 127.0f);
        #pragma unroll
        for (int o = 0; o < DOUT; o++) {
            if (cw & (1u << o))        acc[o] += q;
            if (cw & (1u << (16 + o))) acc[o] -= q;
        }
    }
    #pragma unroll
    for (int o = 0; o < DOUT; o++)
        if (acc[o] != 0.0f) atomicAdd(&g_logits[m * 16 + o], acc[o]);
}

// ---------------------------------------------------------------------------
__global__ void __launch_bounds__(256)
softmax_kernel(const float* __restrict__ b2, float* __restrict__ out) {
    const int m = blockIdx.x * 256 + threadIdx.x;
    const float inv = __uint_as_float(g_maxbits) * (1.0f / 127.0f);

    float l[DOUT];
    float mx = -1e30f;
    #pragma unroll
    for (int o = 0; o < DOUT; o++) {
        l[o] = g_logits[m * 16 + o] * inv + __ldg(b2 + o);
        mx = fmaxf(mx, l[o]);
    }
    float s = 0.0f;
    #pragma unroll
    for (int o = 0; o < DOUT; o++) s += expf(l[o] - mx);
    const float ls = logf(s);
    #pragma unroll
    for (int o = 0; o < DOUT; o++) out[(size_t)m * DOUT + o] = l[o] - mx - ls;
}

// ---------------------------------------------------------------------------
extern "C" void kernel_launch(void* const* d_in, const int* in_sizes, int n_in,
                              void* d_out, int out_size) {
    const float* x  = (const float*)d_in[0];
    const float* w1 = (const float*)d_in[1];
    const float* b1 = (const float*)d_in[2];
    const float* w2 = (const float*)d_in[3];
    const float* b2 = (const float*)d_in[4];
    float* out = (float*)d_out;

    cudaFuncSetAttribute(gemm1_kernel,
                         cudaFuncAttributeMaxDynamicSharedMemorySize, G1_SMEM);

    init_kernel<<<1, 1>>>();
    l2init_kernel<<<(B_ * 16) / 512, 512>>>();
    build_w1_kernel<<<DH / 8, 256>>>(w1);
    build_w2col_kernel<<<DH / 256, 256>>>(w2);
    gemm1_kernel<<<dim3(B_ / G1_TM, DH / G1_TN), 512, G1_SMEM>>>(x, b1);
    l2_partial_kernel<<<dim3(B_ / 512, NSPL), 512>>>();
    softmax_kernel<<<B_ / 256, 256>>>(b2, out);
}